// round 7
// baseline (speedup 1.0000x reference)
#include <cuda_runtime.h>
#include <cuda_bf16.h>

// SoftHistogram via fine-histogram factorization:
//   out[ch][j] = normalize( sum_t counts[ch][t] * W[t][j] )
// W[t][j] = per-pixel-normalized Gaussian weight at x_t = t/TF (round-binning:
// bin = round(x*TF) via the 2^23 magic-FMA trick, rows t = 0..TF inclusive).
//
// R6 vs R5 (27.4us): 4 launches -> 2.
//  - zeroing pass deleted: g_counts starts BSS-zero; hx_out re-zeroes its
//    channel after consuming it, so every launch call sees zeroed counts.
//  - table build fused into the hist launch as extra blocks (MUFU work
//    overlaps the ATOMS-heavy hist blocks).
//  - contraction + normalization fused into one 24-block kernel.

#define TF    2048
#define ROWS  (TF + 1)            // 2049 table rows (bin 0..2048)
#define RPAD  2052                // row pad for g_counts
#define NCH   24                  // 8 * 3 channels
#define BINS  64
#define PPC   (512 * 512)         // pixels per channel
#define HBLK  16                  // hist blocks per channel
#define PXB   (PPC / HBLK)        // 16384 pixels per hist block
#define TBLK  ((ROWS + 7) / 8)    // 257 table blocks (8 rows/block)

__device__ unsigned int g_counts[NCH][RPAD];  // per-channel fine histogram (zero at load)
__device__ float        g_W[ROWS][BINS];      // normalized weight table

// ---------------------------------------------------------------------------
// Kernel 1: fused table-build + histogram.
//  blocks [0, TBLK): weight table, one warp per t-row; lane computes bins
//    {lane, lane+32}, warp-reduces the row sum, writes the normalized pair.
//  blocks [TBLK, TBLK + HBLK*NCH): shared-memory fine histogram, 256 threads,
//    64 pixels/thread via float4. bin = round(x*TF) from the low mantissa
//    bits of fma(x, TF, 2^23): exact for x in [0,1]; mask 0xFFF bounds it.
// ---------------------------------------------------------------------------
__global__ void __launch_bounds__(256) hx_main(const float* __restrict__ x,
                                               const float* __restrict__ centers) {
    __shared__ unsigned int sh[RPAD];
    const int b   = blockIdx.x;
    const int tid = threadIdx.x;

    if (b < TBLK) {
        // ---- weight table ----
        const int warp = tid >> 5;
        const int lane = tid & 31;
        const int t    = b * 8 + warp;
        if (t >= ROWS) return;
        const float xt   = (float)t * (1.0f / (float)TF);
        const float invs = 1.0f / (0.02f + 1e-12f);     // reference SIGMA guard

        float z0 = (xt - __ldg(&centers[lane]))      * invs;
        float z1 = (xt - __ldg(&centers[lane + 32])) * invs;
        float e0 = expf(-0.5f * z0 * z0);
        float e1 = expf(-0.5f * z1 * z1);

        float s = e0 + e1;
#pragma unroll
        for (int off = 16; off > 0; off >>= 1)
            s += __shfl_xor_sync(0xffffffffu, s, off);
        const float r = 1.0f / (s + 1e-12f);

        g_W[t][lane]      = e0 * r;
        g_W[t][lane + 32] = e1 * r;
        return;
    }

    // ---- histogram ----
    for (int i = tid; i < RPAD; i += 256) sh[i] = 0u;
    __syncthreads();

    const int hb  = b - TBLK;
    const int ch  = hb / HBLK;
    const int blk = hb % HBLK;
    const float4* __restrict__ p =
        reinterpret_cast<const float4*>(x + (size_t)ch * PPC + (size_t)blk * PXB);

    const float MAGIC = 8388608.0f;   // 2^23

#pragma unroll 4
    for (int i = 0; i < PXB / (256 * 4); i++) {
        float4 v = p[i * 256 + tid];
        unsigned b0 = __float_as_uint(fmaf(v.x, (float)TF, MAGIC)) & 0xFFFu;
        unsigned b1 = __float_as_uint(fmaf(v.y, (float)TF, MAGIC)) & 0xFFFu;
        unsigned b2 = __float_as_uint(fmaf(v.z, (float)TF, MAGIC)) & 0xFFFu;
        unsigned b3 = __float_as_uint(fmaf(v.w, (float)TF, MAGIC)) & 0xFFFu;
        atomicAdd(&sh[b0], 1u);
        atomicAdd(&sh[b1], 1u);
        atomicAdd(&sh[b2], 1u);
        atomicAdd(&sh[b3], 1u);
    }
    __syncthreads();

    unsigned int* __restrict__ gc = g_counts[ch];
    for (int i = tid; i < ROWS; i += 256) {
        unsigned v = sh[i];
        if (v) atomicAdd(&gc[i], v);     // RED into 2049 words per channel
    }
}

// ---------------------------------------------------------------------------
// Kernel 2: per-channel contraction + both normalizations + re-zero counts.
//   hist[j] = sum_t counts[ch][t] * W[t][j]
//   m = hist/P ; out = m / (sum_j m + 1e-12)
// After reading, zero g_counts[ch] so the next kernel_launch call (graph
// replay) sees pristine counters — keeps the whole launch deterministic.
// ---------------------------------------------------------------------------
__global__ void __launch_bounds__(256) hx_out(float* __restrict__ out) {
    const int ch  = blockIdx.x;
    const int tid = threadIdx.x;

    float acc[BINS];
#pragma unroll
    for (int j = 0; j < BINS; j++) acc[j] = 0.0f;

    for (int t = tid; t < ROWS; t += 256) {
        float c = (float)g_counts[ch][t];
        if (c != 0.0f) {
            const float4* __restrict__ w = reinterpret_cast<const float4*>(g_W[t]);
#pragma unroll
            for (int q = 0; q < 16; q++) {
                float4 ww = w[q];
                acc[4 * q + 0] += c * ww.x;
                acc[4 * q + 1] += c * ww.y;
                acc[4 * q + 2] += c * ww.z;
                acc[4 * q + 3] += c * ww.w;
            }
        }
    }

    // consumed: re-zero this channel's counters for the next launch call
    for (int t = tid; t < ROWS; t += 256) g_counts[ch][t] = 0u;

#pragma unroll
    for (int off = 16; off > 0; off >>= 1) {
#pragma unroll
        for (int j = 0; j < BINS; j++)
            acc[j] += __shfl_down_sync(0xffffffffu, acc[j], off);
    }

    __shared__ float hist[BINS];
    __shared__ float ssum;
    if (tid < BINS) hist[tid] = 0.0f;
    __syncthreads();

    if ((tid & 31) == 0) {               // one leader per warp (8 warps)
#pragma unroll
        for (int j = 0; j < BINS; j++)
            atomicAdd(&hist[j], acc[j]);
    }
    __syncthreads();

    if (tid == 0) {
        float s = 0.0f;
        for (int j = 0; j < BINS; j++) s += hist[j];
        ssum = s * (1.0f / (float)PPC);
    }
    __syncthreads();

    if (tid < BINS) {
        float m = hist[tid] * (1.0f / (float)PPC);   // mean over pixels
        out[ch * BINS + tid] = m / (ssum + 1e-12f);  // per-image normalize
    }
}

// ---------------------------------------------------------------------------
extern "C" void kernel_launch(void* const* d_in, const int* in_sizes, int n_in,
                              void* d_out, int out_size) {
    const float* x       = (const float*)d_in[0];   // (8,3,512,512) fp32
    const float* centers = (const float*)d_in[1];   // (64,) fp32
    float* out           = (float*)d_out;           // (8,3,64) fp32

    hx_main<<<TBLK + HBLK * NCH, 256>>>(x, centers);
    hx_out<<<NCH, 256>>>(out);
}

// round 8
// speedup vs baseline: 1.7436x; 1.7436x over previous
#include <cuda_runtime.h>
#include <cuda_bf16.h>

// SoftHistogram via fine-histogram factorization:
//   out[ch][j] = normalize( sum_t counts[ch][t] * W[t][j] )
// W[t][j] = per-pixel-normalized Gaussian weight at x_t = t/TF (round-binning:
// bin = round(x*TF) via the 2^23 magic-FMA trick, rows t = 0..TF inclusive).
//
// R7 vs R6 (37.0us; best 27.4us): hx_out re-parallelized to grid (8,24) with
// a threadfence last-block reduction (R6's 24-block fused version serialized
// the 12.6MB L2 table stream onto 24 SMs -> 32.3us). Still 2 launches.

#define TF    2048
#define ROWS  (TF + 1)            // 2049 table rows (bin 0..2048)
#define RPAD  2052                // row pad for g_counts
#define NCH   24                  // 8 * 3 channels
#define BINS  64
#define PPC   (512 * 512)         // pixels per channel
#define HBLK  16                  // hist blocks per channel
#define PXB   (PPC / HBLK)        // 16384 pixels per hist block
#define TBLK  ((ROWS + 7) / 8)    // 257 table blocks (8 rows/block)
#define NSPL  8                   // contraction splits per channel
#define RSPL  257                 // rows per split (8*257 >= 2049)

__device__ unsigned int g_counts[NCH][RPAD];  // per-channel fine histogram (BSS zero)
__device__ float        g_W[ROWS][BINS];      // normalized weight table
__device__ float        g_hist[NCH][BINS];    // cross-block accumulators (BSS zero)
__device__ unsigned int g_done[NCH];          // completion counters (BSS zero)

// ---------------------------------------------------------------------------
// Kernel 1: fused table-build + histogram.
//  blocks [0, TBLK): weight table, one warp per t-row; lane computes bins
//    {lane, lane+32}, warp-reduces the row sum, writes the normalized pair.
//  blocks [TBLK, TBLK + HBLK*NCH): shared-memory fine histogram, 256 threads,
//    64 pixels/thread via float4. bin = round(x*TF) from the low mantissa
//    bits of fma(x, TF, 2^23): exact for x in [0,1]; mask 0xFFF bounds it.
// ---------------------------------------------------------------------------
__global__ void __launch_bounds__(256) hx_main(const float* __restrict__ x,
                                               const float* __restrict__ centers) {
    __shared__ unsigned int sh[RPAD];
    const int b   = blockIdx.x;
    const int tid = threadIdx.x;

    if (b < TBLK) {
        // ---- weight table ----
        const int warp = tid >> 5;
        const int lane = tid & 31;
        const int t    = b * 8 + warp;
        if (t >= ROWS) return;
        const float xt   = (float)t * (1.0f / (float)TF);
        const float invs = 1.0f / (0.02f + 1e-12f);     // reference SIGMA guard

        float z0 = (xt - __ldg(&centers[lane]))      * invs;
        float z1 = (xt - __ldg(&centers[lane + 32])) * invs;
        float e0 = expf(-0.5f * z0 * z0);
        float e1 = expf(-0.5f * z1 * z1);

        float s = e0 + e1;
#pragma unroll
        for (int off = 16; off > 0; off >>= 1)
            s += __shfl_xor_sync(0xffffffffu, s, off);
        const float r = 1.0f / (s + 1e-12f);

        g_W[t][lane]      = e0 * r;
        g_W[t][lane + 32] = e1 * r;
        return;
    }

    // ---- histogram ----
    for (int i = tid; i < RPAD; i += 256) sh[i] = 0u;
    __syncthreads();

    const int hb  = b - TBLK;
    const int ch  = hb / HBLK;
    const int blk = hb % HBLK;
    const float4* __restrict__ p =
        reinterpret_cast<const float4*>(x + (size_t)ch * PPC + (size_t)blk * PXB);

    const float MAGIC = 8388608.0f;   // 2^23

#pragma unroll 4
    for (int i = 0; i < PXB / (256 * 4); i++) {
        float4 v = p[i * 256 + tid];
        unsigned b0 = __float_as_uint(fmaf(v.x, (float)TF, MAGIC)) & 0xFFFu;
        unsigned b1 = __float_as_uint(fmaf(v.y, (float)TF, MAGIC)) & 0xFFFu;
        unsigned b2 = __float_as_uint(fmaf(v.z, (float)TF, MAGIC)) & 0xFFFu;
        unsigned b3 = __float_as_uint(fmaf(v.w, (float)TF, MAGIC)) & 0xFFFu;
        atomicAdd(&sh[b0], 1u);
        atomicAdd(&sh[b1], 1u);
        atomicAdd(&sh[b2], 1u);
        atomicAdd(&sh[b3], 1u);
    }
    __syncthreads();

    unsigned int* __restrict__ gc = g_counts[ch];
    for (int i = tid; i < ROWS; i += 256) {
        unsigned v = sh[i];
        if (v) atomicAdd(&gc[i], v);     // RED into 2049 words per channel
    }
}

// ---------------------------------------------------------------------------
// Kernel 2: contraction + normalization, grid (NSPL, NCH), last-block pattern.
// Block (split, ch): partial hist over rows [split*RSPL, ...), smem combine
// to 64 values, RED.F32 into g_hist[ch]; re-zero its g_counts slice. The 8th
// arriver per channel normalizes, writes out[ch], resets g_hist/g_done.
// ---------------------------------------------------------------------------
__global__ void __launch_bounds__(256) hx_out(float* __restrict__ out) {
    const int split = blockIdx.x;
    const int ch    = blockIdx.y;
    const int tid   = threadIdx.x;
    const int warp  = tid >> 5;
    const int lane  = tid & 31;

    float acc[BINS];
#pragma unroll
    for (int j = 0; j < BINS; j++) acc[j] = 0.0f;

    const int r0 = split * RSPL;
    const int r1 = min(r0 + RSPL, ROWS);
    for (int r = r0 + tid; r < r1; r += 256) {
        float c = (float)g_counts[ch][r];
        const float4* __restrict__ w = reinterpret_cast<const float4*>(g_W[r]);
#pragma unroll
        for (int q = 0; q < 16; q++) {
            float4 ww = w[q];
            acc[4 * q + 0] += c * ww.x;
            acc[4 * q + 1] += c * ww.y;
            acc[4 * q + 2] += c * ww.z;
            acc[4 * q + 3] += c * ww.w;
        }
    }

    // consumed: re-zero this slice for the next graph replay
    for (int r = r0 + tid; r < r1; r += 256) g_counts[ch][r] = 0u;

    // warp tree-reduce 8 warps -> 8 partial vectors
#pragma unroll
    for (int off = 16; off > 0; off >>= 1) {
#pragma unroll
        for (int j = 0; j < BINS; j++)
            acc[j] += __shfl_down_sync(0xffffffffu, acc[j], off);
    }

    __shared__ float part[8][BINS];
    if (lane == 0) {
#pragma unroll
        for (int j = 0; j < BINS; j++) part[warp][j] = acc[j];
    }
    __syncthreads();

    if (tid < BINS) {
        float s = 0.0f;
#pragma unroll
        for (int w = 0; w < 8; w++) s += part[w][tid];
        atomicAdd(&g_hist[ch][tid], s);           // 64 REDs per block
    }
    __threadfence();
    __syncthreads();

    __shared__ unsigned int s_last;
    if (tid == 0)
        s_last = (atomicAdd(&g_done[ch], 1u) == NSPL - 1u) ? 1u : 0u;
    __syncthreads();
    if (!s_last) return;

    // ---- last block for this channel: normalize + reset ----
    float m = 0.0f;
    if (tid < BINS)
        m = *((volatile float*)&g_hist[ch][tid]) * (1.0f / (float)PPC);

    float t = (tid < BINS) ? m : 0.0f;            // warps 0,1 carry data
#pragma unroll
    for (int off = 16; off > 0; off >>= 1)
        t += __shfl_xor_sync(0xffffffffu, t, off);

    __shared__ float ws[8];
    if (lane == 0) ws[warp] = t;
    __syncthreads();

    if (tid < BINS) {
        float tot = ws[0] + ws[1];
        out[ch * BINS + tid] = m / (tot + 1e-12f);
        g_hist[ch][tid] = 0.0f;                   // reset for next replay
    }
    if (tid == 0) g_done[ch] = 0u;
}

// ---------------------------------------------------------------------------
extern "C" void kernel_launch(void* const* d_in, const int* in_sizes, int n_in,
                              void* d_out, int out_size) {
    const float* x       = (const float*)d_in[0];   // (8,3,512,512) fp32
    const float* centers = (const float*)d_in[1];   // (64,) fp32
    float* out           = (float*)d_out;           // (8,3,64) fp32

    hx_main<<<TBLK + HBLK * NCH, 256>>>(x, centers);
    hx_out<<<dim3(NSPL, NCH), 256>>>(out);
}

// round 12
// speedup vs baseline: 1.9299x; 1.1068x over previous
#include <cuda_runtime.h>
#include <cuda_bf16.h>

// SoftHistogram via fine-histogram factorization:
//   out[ch][j] = normalize( sum_t counts[ch][t] * W[t][j] )
// W[t][j] = per-pixel-normalized Gaussian weight at x_t = t/TF (round-binning:
// bin = round(x*TF) via the 2^23 magic-FMA trick, rows t = 0..TF inclusive).
//
// R11 = R10 resubmitted (R10 bench was an infra failure, never ran).
// R10 vs R8 (FAILED 7.9e-3): R8's transposed contraction had a read/zero race
// on g_counts — row r is read by 16 threads but zeroed by one, with no sync
// between. Fix: __syncthreads() between the contraction reads and the
// re-zero loop. Everything else identical to R8.

#define TF    2048
#define ROWS  (TF + 1)            // 2049 table rows (bin 0..2048)
#define RPAD  2052                // row pad for g_counts
#define NCH   24                  // 8 * 3 channels
#define BINS  64
#define PPC   (512 * 512)         // pixels per channel
#define HBLK  16                  // hist blocks per channel
#define PXB   (PPC / HBLK)        // 16384 pixels per hist block
#define TBLK  ((ROWS + 7) / 8)    // 257 table blocks (8 rows/block)
#define NSPL  8                   // contraction splits per channel
#define RSPL  257                 // rows per split (8*257 >= 2049)

__device__ unsigned int g_counts[NCH][RPAD];  // per-channel fine histogram (BSS zero)
__device__ float        g_W[ROWS][BINS];      // normalized weight table
__device__ float        g_hist[NCH][BINS];    // cross-block accumulators (BSS zero)
__device__ unsigned int g_done[NCH];          // completion counters (BSS zero)

// ---------------------------------------------------------------------------
// Kernel 1: fused table-build + histogram.
//  blocks [0, TBLK): weight table, one warp per t-row; lane computes bins
//    {lane, lane+32}, warp-reduces the row sum, writes the normalized pair.
//  blocks [TBLK, TBLK + HBLK*NCH): shared-memory fine histogram, 256 threads,
//    64 pixels/thread via float4. bin = round(x*TF) from the low mantissa
//    bits of fma(x, TF, 2^23): exact for x in [0,1]; mask 0xFFF bounds it.
// ---------------------------------------------------------------------------
__global__ void __launch_bounds__(256) hx_main(const float* __restrict__ x,
                                               const float* __restrict__ centers) {
    __shared__ unsigned int sh[RPAD];
    const int b   = blockIdx.x;
    const int tid = threadIdx.x;

    if (b < TBLK) {
        // ---- weight table ----
        const int warp = tid >> 5;
        const int lane = tid & 31;
        const int t    = b * 8 + warp;
        if (t >= ROWS) return;
        const float xt   = (float)t * (1.0f / (float)TF);
        const float invs = 1.0f / (0.02f + 1e-12f);     // reference SIGMA guard

        float z0 = (xt - __ldg(&centers[lane]))      * invs;
        float z1 = (xt - __ldg(&centers[lane + 32])) * invs;
        float e0 = expf(-0.5f * z0 * z0);
        float e1 = expf(-0.5f * z1 * z1);

        float s = e0 + e1;
#pragma unroll
        for (int off = 16; off > 0; off >>= 1)
            s += __shfl_xor_sync(0xffffffffu, s, off);
        const float r = 1.0f / (s + 1e-12f);

        g_W[t][lane]      = e0 * r;
        g_W[t][lane + 32] = e1 * r;
        return;
    }

    // ---- histogram ----
    for (int i = tid; i < RPAD; i += 256) sh[i] = 0u;
    __syncthreads();

    const int hb  = b - TBLK;
    const int ch  = hb / HBLK;
    const int blk = hb % HBLK;
    const float4* __restrict__ p =
        reinterpret_cast<const float4*>(x + (size_t)ch * PPC + (size_t)blk * PXB);

    const float MAGIC = 8388608.0f;   // 2^23

#pragma unroll 4
    for (int i = 0; i < PXB / (256 * 4); i++) {
        float4 v = p[i * 256 + tid];
        unsigned b0 = __float_as_uint(fmaf(v.x, (float)TF, MAGIC)) & 0xFFFu;
        unsigned b1 = __float_as_uint(fmaf(v.y, (float)TF, MAGIC)) & 0xFFFu;
        unsigned b2 = __float_as_uint(fmaf(v.z, (float)TF, MAGIC)) & 0xFFFu;
        unsigned b3 = __float_as_uint(fmaf(v.w, (float)TF, MAGIC)) & 0xFFFu;
        atomicAdd(&sh[b0], 1u);
        atomicAdd(&sh[b1], 1u);
        atomicAdd(&sh[b2], 1u);
        atomicAdd(&sh[b3], 1u);
    }
    __syncthreads();

    unsigned int* __restrict__ gc = g_counts[ch];
    for (int i = tid; i < ROWS; i += 256) {
        unsigned v = sh[i];
        if (v) atomicAdd(&gc[i], v);     // RED into 2049 words per channel
    }
}

// ---------------------------------------------------------------------------
// Kernel 2: contraction + normalization, grid (NSPL, NCH), last-block pattern.
// Transposed layout: thread owns bin-group j4=(tid&15)*4 and row-slice
// rs=tid>>4; accumulates acc[4] over rows with stride 16. float4 W loads are
// coalesced across lanes 0-15; counts are broadcast loads. 16x64 smem combine
// -> 64 REDs into g_hist[ch]. Last arriver per channel normalizes, writes
// out[ch], resets state for the next graph replay.
// ---------------------------------------------------------------------------
__global__ void __launch_bounds__(256) hx_out(float* __restrict__ out) {
    const int split = blockIdx.x;
    const int ch    = blockIdx.y;
    const int tid   = threadIdx.x;
    const int jg    = tid & 15;          // bin group (4 bins)
    const int rs    = tid >> 4;          // row slice 0..15

    const int r0 = split * RSPL;
    const int r1 = min(r0 + RSPL, ROWS);

    float ax = 0.f, ay = 0.f, az = 0.f, aw = 0.f;
    const float4* __restrict__ W4 = reinterpret_cast<const float4*>(g_W);
    const unsigned int* __restrict__ gc = g_counts[ch];

    for (int r = r0 + rs; r < r1; r += 16) {
        float  c = (float)gc[r];
        float4 w = W4[r * 16 + jg];
        ax = fmaf(c, w.x, ax);
        ay = fmaf(c, w.y, ay);
        az = fmaf(c, w.z, az);
        aw = fmaf(c, w.w, aw);
    }

    // All threads must finish READING this slice before anyone zeroes it:
    // row r is read by 16 threads but zeroed by one (this was the R8 race).
    __syncthreads();

    // consumed: re-zero this slice for the next graph replay
    for (int r = r0 + tid; r < r1; r += 256) g_counts[ch][r] = 0u;

    __shared__ float part[16][BINS + 4];        // +4 pad: kill bank conflicts
    part[rs][jg * 4 + 0] = ax;
    part[rs][jg * 4 + 1] = ay;
    part[rs][jg * 4 + 2] = az;
    part[rs][jg * 4 + 3] = aw;
    __syncthreads();

    if (tid < BINS) {
        float s = 0.0f;
#pragma unroll
        for (int k = 0; k < 16; k++) s += part[k][tid];
        atomicAdd(&g_hist[ch][tid], s);         // 64 REDs per block
    }
    __threadfence();
    __syncthreads();

    __shared__ unsigned int s_last;
    if (tid == 0)
        s_last = (atomicAdd(&g_done[ch], 1u) == NSPL - 1u) ? 1u : 0u;
    __syncthreads();
    if (!s_last) return;

    // ---- last block for this channel: normalize + reset ----
    const int warp = tid >> 5;
    const int lane = tid & 31;

    float m = 0.0f;
    if (tid < BINS)
        m = *((volatile float*)&g_hist[ch][tid]) * (1.0f / (float)PPC);

    float t = (tid < BINS) ? m : 0.0f;          // warps 0,1 carry data
#pragma unroll
    for (int off = 16; off > 0; off >>= 1)
        t += __shfl_xor_sync(0xffffffffu, t, off);

    __shared__ float ws[8];
    if (lane == 0) ws[warp] = t;
    __syncthreads();

    if (tid < BINS) {
        float tot = ws[0] + ws[1];
        out[ch * BINS + tid] = m / (tot + 1e-12f);
        g_hist[ch][tid] = 0.0f;                 // reset for next replay
    }
    if (tid == 0) g_done[ch] = 0u;
}

// ---------------------------------------------------------------------------
extern "C" void kernel_launch(void* const* d_in, const int* in_sizes, int n_in,
                              void* d_out, int out_size) {
    const float* x       = (const float*)d_in[0];   // (8,3,512,512) fp32
    const float* centers = (const float*)d_in[1];   // (64,) fp32
    float* out           = (float*)d_out;           // (8,3,64) fp32

    hx_main<<<TBLK + HBLK * NCH, 256>>>(x, centers);
    hx_out<<<dim3(NSPL, NCH), 256>>>(out);
}